// round 17
// baseline (speedup 1.0000x reference)
#include <cuda_runtime.h>
#include <cuda_fp16.h>
#include <math.h>
#include <stdint.h>

#define B_  8
#define T_  1024
#define E_  1024
#define H_  16
#define DH_ 64

// Scratch (__device__ globals: allocation-free rule; zero-initialized)
__device__ float  g_bcomb[E_];                                       // Wc*bo + bc
__device__ __align__(16) __half g_xh    [(size_t)B_ * T_ * E_];      // 16 MB
__device__ __align__(16) __half g_wih   [(size_t)3 * E_ * E_];       // 6 MB
__device__ __align__(16) __half g_wch   [(size_t)E_ * E_];           // 2 MB
__device__ __align__(16) __half g_woTh  [(size_t)E_ * E_];           // 2 MB
__device__ __align__(16) __half g_qkvh  [(size_t)B_ * T_ * 3 * E_];  // 48 MB
__device__ __align__(16) __half g_atth  [(size_t)B_ * T_ * E_];      // 16 MB
__device__ __align__(16) __half g_wcombh[(size_t)E_ * E_];           // 2 MB

// ---------------------------------------------------------------------------
__device__ __forceinline__ uint32_t sptr(const void* p) {
    return (uint32_t)__cvta_generic_to_shared(p);
}
__device__ __forceinline__ void cpa16(uint32_t dst, const void* src) {
    asm volatile("cp.async.cg.shared.global [%0], [%1], 16;\n" :: "r"(dst), "l"(src));
}
__device__ __forceinline__ void mma_f16(
    float& c0, float& c1, float& c2, float& c3,
    uint32_t a0, uint32_t a1, uint32_t a2, uint32_t a3,
    uint32_t b0, uint32_t b1)
{
    asm volatile(
        "mma.sync.aligned.m16n8k16.row.col.f32.f16.f16.f32 "
        "{%0,%1,%2,%3},{%4,%5,%6,%7},{%8,%9},{%0,%1,%2,%3};"
        : "+f"(c0), "+f"(c1), "+f"(c2), "+f"(c3)
        : "r"(a0), "r"(a1), "r"(a2), "r"(a3), "r"(b0), "r"(b1));
}
__device__ __forceinline__ void ldm_x4(uint32_t& r0, uint32_t& r1,
                                       uint32_t& r2, uint32_t& r3, uint32_t addr) {
    asm volatile("ldmatrix.sync.aligned.m8n8.x4.shared.b16 {%0,%1,%2,%3}, [%4];"
                 : "=r"(r0), "=r"(r1), "=r"(r2), "=r"(r3) : "r"(addr));
}
__device__ __forceinline__ uint32_t h2u(__half2 h) {
    return *reinterpret_cast<uint32_t*>(&h);
}

// x -> fp16 (rn) --------------------------------------------------------------
__global__ void __launch_bounds__(256) cvt_xh(const float* __restrict__ in) {
    int i = blockIdx.x * blockDim.x + threadIdx.x;
    const int n4 = B_ * T_ * E_ / 4;
    if (i < n4) {
        float4 v = reinterpret_cast<const float4*>(in)[i];
        __half2 h01 = __floats2half2_rn(v.x, v.y);
        __half2 h23 = __floats2half2_rn(v.z, v.w);
        uint2 u;
        u.x = h2u(h01);
        u.y = h2u(h23);
        reinterpret_cast<uint2*>(g_xh)[i] = u;
    }
}

// wi -> half; wc -> half ------------------------------------------------------
__global__ void __launch_bounds__(256) cvt_w(const float* __restrict__ wi,
                                             const float* __restrict__ wc) {
    int i = blockIdx.x * blockDim.x + threadIdx.x;
    const int n_i = 3 * E_ * E_ / 4;
    const int n_o = E_ * E_ / 4;
    const float4* src;
    __half* dsth;
    int j;
    if (i < n_i)             { src = (const float4*)wi; dsth = g_wih; j = i; }
    else if (i < n_i + n_o)  { src = (const float4*)wc; dsth = g_wch; j = i - n_i; }
    else return;
    float4 v = src[j];
    __half2 h01 = __floats2half2_rn(v.x, v.y);
    __half2 h23 = __floats2half2_rn(v.z, v.w);
    uint2 u;
    u.x = h2u(h01);
    u.y = h2u(h23);
    reinterpret_cast<uint2*>(dsth)[j] = u;
}

// 1024x1024 transpose + half convert: g_woTh = half(Wo^T) --------------------
__global__ void __launch_bounds__(256) transpose_wo(const float* __restrict__ wo) {
    __shared__ float t[32][33];
    int x = blockIdx.x * 32 + threadIdx.x;
    int y = blockIdx.y * 32 + threadIdx.y;
#pragma unroll
    for (int i = 0; i < 32; i += 8)
        t[threadIdx.y + i][threadIdx.x] = wo[(size_t)(y + i) * E_ + x];
    __syncthreads();
    x = blockIdx.y * 32 + threadIdx.x;
    y = blockIdx.x * 32 + threadIdx.y;
#pragma unroll
    for (int i = 0; i < 32; i += 8)
        g_woTh[(size_t)(y + i) * E_ + x] = __float2half_rn(t[threadIdx.x][threadIdx.y + i]);
}

// b_comb = Wc * bo + bc (fp32, warp per row) ---------------------------------
__global__ void __launch_bounds__(256) bcomb_k(const float* __restrict__ wc,
                                               const float* __restrict__ bo,
                                               const float* __restrict__ bc) {
    int row  = blockIdx.x * 8 + (threadIdx.x >> 5);
    int lane = threadIdx.x & 31;
    const float* wr = wc + (size_t)row * E_;
    float s = 0.f;
    for (int j = lane; j < E_; j += 32) s += wr[j] * bo[j];
#pragma unroll
    for (int o = 16; o; o >>= 1) s += __shfl_xor_sync(0xffffffffu, s, o);
    if (lane == 0) g_bcomb[row] = bc[row] + s;
}

// ---------------------------------------------------------------------------
// FP16 wcomb GEMM (R14/R16, passing): g_wcombh = half(Wc @ Wo).
// ---------------------------------------------------------------------------
__global__ void __launch_bounds__(256, 2) gemm_wcomb_h()
{
    const __half* A  = g_wch;
    const __half* Bm = g_woTh;
    const int N = E_, K = E_;
    __shared__ __half As[2][128][24];
    __shared__ __half Bs[2][128][24];

    const int tid  = threadIdx.x;
    const int lane = tid & 31;
    const int wid  = tid >> 5;
    const int gid  = lane >> 2;
    const int tig  = lane & 3;
    const int wm   = (wid >> 2) * 64;
    const int wn   = (wid & 3) * 32;
    const int bm   = blockIdx.y * 128;
    const int bn   = blockIdx.x * 128;

    float acc[4][4][4];
#pragma unroll
    for (int mt = 0; mt < 4; mt++)
#pragma unroll
        for (int nt = 0; nt < 4; nt++)
#pragma unroll
            for (int r = 0; r < 4; r++) acc[mt][nt][r] = 0.f;

    auto issue = [&](int k0, int s) {
        int row = tid >> 1;
        int ci  = tid & 1;
        cpa16(sptr(&As[s][row][ci * 8]), A  + (size_t)(bm + row) * K + k0 + ci * 8);
        cpa16(sptr(&Bs[s][row][ci * 8]), Bm + (size_t)(bn + row) * K + k0 + ci * 8);
    };

    issue(0, 0);
    asm volatile("cp.async.commit_group;\n" ::: "memory");

    const int NIT = K / 16;
    for (int it = 0; it < NIT; it++) {
        asm volatile("cp.async.wait_group 0;\n" ::: "memory");
        __syncthreads();
        if (it + 1 < NIT) {
            issue((it + 1) * 16, (it + 1) & 1);
            asm volatile("cp.async.commit_group;\n" ::: "memory");
        }
        const int s = it & 1;
        uint32_t a[4][4], b[4][2];
#pragma unroll
        for (int mt = 0; mt < 4; mt++) {
            int r0 = wm + mt * 16 + gid;
            int r1 = r0 + 8;
            a[mt][0] = *reinterpret_cast<const uint32_t*>(&As[s][r0][2 * tig    ]);
            a[mt][1] = *reinterpret_cast<const uint32_t*>(&As[s][r1][2 * tig    ]);
            a[mt][2] = *reinterpret_cast<const uint32_t*>(&As[s][r0][2 * tig + 8]);
            a[mt][3] = *reinterpret_cast<const uint32_t*>(&As[s][r1][2 * tig + 8]);
        }
#pragma unroll
        for (int nt = 0; nt < 4; nt++) {
            int c0i = wn + nt * 8 + gid;
            b[nt][0] = *reinterpret_cast<const uint32_t*>(&Bs[s][c0i][2 * tig    ]);
            b[nt][1] = *reinterpret_cast<const uint32_t*>(&Bs[s][c0i][2 * tig + 8]);
        }
#pragma unroll
        for (int mt = 0; mt < 4; mt++)
#pragma unroll
            for (int nt = 0; nt < 4; nt++)
                mma_f16(acc[mt][nt][0], acc[mt][nt][1], acc[mt][nt][2], acc[mt][nt][3],
                        a[mt][0], a[mt][1], a[mt][2], a[mt][3], b[nt][0], b[nt][1]);
    }

#pragma unroll
    for (int mt = 0; mt < 4; mt++) {
#pragma unroll
        for (int nt = 0; nt < 4; nt++) {
            int row = bm + wm + mt * 16 + gid;
            int col = bn + wn + nt * 8 + tig * 2;
            *reinterpret_cast<__half2*>(&g_wcombh[(size_t)row * N + col]) =
                __floats2half2_rn(acc[mt][nt][0], acc[mt][nt][1]);
            *reinterpret_cast<__half2*>(&g_wcombh[(size_t)(row + 8) * N + col]) =
                __floats2half2_rn(acc[mt][nt][2], acc[mt][nt][3]);
        }
    }
}

// ---------------------------------------------------------------------------
// Big FP16 GEMM: 256x128 CTA tile, 8 warps 4(M)x2(N) of 64x64, BK=16.
// Stride-24-half rows (48B): ldmatrix 8-row phases hit word offsets
// 12i mod 32 = {0,12,24,4,16,28,8,20} -> conflict-free. Fragments loaded
// with ldmatrix.x4 (8 instr/warp/iter vs 32 scalar LDS).
// 2-stage cp.async, one __syncthreads per K-step. Static smem 36,864 B.
// ---------------------------------------------------------------------------
__device__ __forceinline__ void gemm_f16_big2(
    const __half* __restrict__ A, const __half* __restrict__ Bm,
    const float* __restrict__ bias, float* __restrict__ Cf,
    __half* __restrict__ Ch, int N, int K)
{
    __shared__ __half As[2][256][24];
    __shared__ __half Bs[2][128][24];

    const int tid  = threadIdx.x;
    const int lane = tid & 31;
    const int wid  = tid >> 5;
    const int gid  = lane >> 2;
    const int tig  = lane & 3;
    const int wm   = (wid >> 1) * 64;
    const int wn   = (wid & 1) * 64;
    const int bm   = blockIdx.y * 256;
    const int bn   = blockIdx.x * 128;

    // ldmatrix source addresses (per thread), stage 0; stage stride in bytes.
    // A x4 for tile mt: matrices {rows 0-7 k0-7, rows 8-15 k0-7,
    //                             rows 0-7 k8-15, rows 8-15 k8-15}
    const uint32_t aAddr0 = sptr(&As[0][wm + (lane & 15)][(lane >> 4) * 8]);
    // B x4 for pair p (nt=2p,2p+1): {n0-7 k0-7, n0-7 k8-15, n8-15 k0-7, n8-15 k8-15}
    const uint32_t bAddr0 = sptr(&Bs[0][wn + ((lane >> 4) << 3) + (lane & 7)]
                                       [((lane >> 3) & 1) * 8]);
    const uint32_t aStage = 256 * 24 * 2;   // bytes per A stage
    const uint32_t bStage = 128 * 24 * 2;
    const uint32_t tile16 = 16 * 24 * 2;    // 16 rows

    float acc[4][8][4];
#pragma unroll
    for (int mt = 0; mt < 4; mt++)
#pragma unroll
        for (int nt = 0; nt < 8; nt++)
#pragma unroll
            for (int r = 0; r < 4; r++) acc[mt][nt][r] = 0.f;

    auto issue = [&](int k0, int s) {
#pragma unroll
        for (int i = 0; i < 2; i++) {            // A: 256 rows x 2 chunks
            int idx = tid + i * 256;
            int row = idx >> 1;
            int ci  = idx & 1;
            cpa16(sptr(&As[s][row][ci * 8]),
                  A + (size_t)(bm + row) * K + k0 + ci * 8);
        }
        {                                        // B: 128 rows x 2 chunks
            int row = tid >> 1;
            int ci  = tid & 1;
            cpa16(sptr(&Bs[s][row][ci * 8]),
                  Bm + (size_t)(bn + row) * K + k0 + ci * 8);
        }
    };

    issue(0, 0);
    asm volatile("cp.async.commit_group;\n" ::: "memory");

    const int NIT = K / 16;
    for (int it = 0; it < NIT; it++) {
        asm volatile("cp.async.wait_group 0;\n" ::: "memory");
        __syncthreads();
        if (it + 1 < NIT) {
            issue((it + 1) * 16, (it + 1) & 1);
            asm volatile("cp.async.commit_group;\n" ::: "memory");
        }

        const int s = it & 1;
        const uint32_t aB = aAddr0 + s * aStage;
        const uint32_t bB = bAddr0 + s * bStage;
        uint32_t a[4][4], b[8][2];
#pragma unroll
        for (int mt = 0; mt < 4; mt++)
            ldm_x4(a[mt][0], a[mt][1], a[mt][2], a[mt][3], aB + mt * tile16);
#pragma unroll
        for (int p = 0; p < 4; p++)
            ldm_x4(b[2 * p][0], b[2 * p][1], b[2 * p + 1][0], b[2 * p + 1][1],
                   bB + p * tile16);
#pragma unroll
        for (int mt = 0; mt < 4; mt++)
#pragma unroll
            for (int nt = 0; nt < 8; nt++)
                mma_f16(acc[mt][nt][0], acc[mt][nt][1], acc[mt][nt][2], acc[mt][nt][3],
                        a[mt][0], a[mt][1], a[mt][2], a[mt][3], b[nt][0], b[nt][1]);
    }

#pragma unroll
    for (int mt = 0; mt < 4; mt++) {
#pragma unroll
        for (int nt = 0; nt < 8; nt++) {
            int row = bm + wm + mt * 16 + gid;
            int col = bn + wn + nt * 8 + tig * 2;
            float bv0 = bias[col], bv1 = bias[col + 1];
            float v0 = acc[mt][nt][0] + bv0;
            float v1 = acc[mt][nt][1] + bv1;
            float v2 = acc[mt][nt][2] + bv0;
            float v3 = acc[mt][nt][3] + bv1;
            if (Ch) {
                *reinterpret_cast<__half2*>(&Ch[(size_t)row * N + col]) =
                    __floats2half2_rn(v0, v1);
                *reinterpret_cast<__half2*>(&Ch[(size_t)(row + 8) * N + col]) =
                    __floats2half2_rn(v2, v3);
            } else {
                *reinterpret_cast<float2*>(Cf + (size_t)row * N + col) = make_float2(v0, v1);
                *reinterpret_cast<float2*>(Cf + (size_t)(row + 8) * N + col) = make_float2(v2, v3);
            }
        }
    }
}

__global__ void __launch_bounds__(256, 1) gemm_in_h(const float* __restrict__ bi) {
    gemm_f16_big2(g_xh, g_wih, bi, nullptr, g_qkvh, 3 * E_, E_);
}
__global__ void __launch_bounds__(256, 1) gemm_fin_h(float* __restrict__ out) {
    gemm_f16_big2(g_atth, g_wcombh, g_bcomb, out, nullptr, E_, E_);
}

// ---------------------------------------------------------------------------
// FP16 tensor-core causal flash attention (R16, passing).
// ---------------------------------------------------------------------------
#define KT_ 32
#define FSH 72

__global__ void __launch_bounds__(128, 3) flash_attn()
{
    __shared__ __align__(16) __half Ks[2][KT_][FSH];
    __shared__ __align__(16) __half Vs[2][KT_][FSH];

    const __half* qkv = g_qkvh;
    const int tid  = threadIdx.x;
    const int lane = tid & 31;
    const int w    = tid >> 5;
    const int gid  = lane >> 2;
    const int tig  = lane & 3;
    const int qb   = gridDim.x - 1 - blockIdx.x;
    const int b    = blockIdx.y >> 4;
    const int h    = blockIdx.y & 15;
    const size_t base = (size_t)b * T_ * 3 * E_ + (size_t)h * DH_;

    // ---- stage Q (64x64 half) into Ks[0..1] ----
#pragma unroll
    for (int i = 0; i < 4; i++) {
        int idx = tid + i * 128;
        int row = idx >> 3;
        int c8  = (idx & 7) * 8;
        cpa16(sptr(&Ks[row >> 5][row & 31][c8]),
              qkv + base + (size_t)(qb * 64 + row) * 3 * E_ + c8);
    }
    asm volatile("cp.async.commit_group;\n" ::: "memory");
    asm volatile("cp.async.wait_group 0;\n" ::: "memory");
    __syncthreads();

    // ---- Q fragments (half2, scale 1/8 folded) ----
    const __half2 s8 = __float2half2_rn(0.125f);
    uint32_t qf[4][4];
    {
        const int r0 = w * 16 + gid;
        const int r1 = r0 + 8;
#pragma unroll
        for (int kc = 0; kc < 4; kc++) {
            __half2 t0 = *reinterpret_cast<const __half2*>(&Ks[r0 >> 5][r0 & 31][kc * 16 + 2 * tig    ]);
            __half2 t1 = *reinterpret_cast<const __half2*>(&Ks[r1 >> 5][r1 & 31][kc * 16 + 2 * tig    ]);
            __half2 t2 = *reinterpret_cast<const __half2*>(&Ks[r0 >> 5][r0 & 31][kc * 16 + 2 * tig + 8]);
            __half2 t3 = *reinterpret_cast<const __half2*>(&Ks[r1 >> 5][r1 & 31][kc * 16 + 2 * tig + 8]);
            qf[kc][0] = h2u(__hmul2(t0, s8));
            qf[kc][1] = h2u(__hmul2(t1, s8));
            qf[kc][2] = h2u(__hmul2(t2, s8));
            qf[kc][3] = h2u(__hmul2(t3, s8));
        }
    }
    __syncthreads();

    auto issue_kv = [&](int kb, int s) {
#pragma unroll
        for (int i = 0; i < 2; i++) {
            int idx = tid + i * 128;
            int row = idx >> 3;
            int c8  = (idx & 7) * 8;
            size_t tok = base + (size_t)(kb * KT_ + row) * 3 * E_;
            cpa16(sptr(&Ks[s][row][c8]), qkv + tok + E_ + c8);
            cpa16(sptr(&Vs[s][row][c8]), qkv + tok + 2 * E_ + c8);
        }
    };

    issue_kv(0, 0);
    asm volatile("cp.async.commit_group;\n" ::: "memory");

    float m0 = -1e30f, m1 = -1e30f, l0 = 0.f, l1 = 0.f;
    float oacc[8][4];
#pragma unroll
    for (int n = 0; n < 8; n++)
#pragma unroll
        for (int r = 0; r < 4; r++) oacc[n][r] = 0.f;

    const int nkb = 2 * qb + 2;
    for (int kb = 0; kb < nkb; kb++) {
        asm volatile("cp.async.wait_group 0;\n" ::: "memory");
        __syncthreads();
        if (kb + 1 < nkb) {
            issue_kv(kb + 1, (kb + 1) & 1);
            asm volatile("cp.async.commit_group;\n" ::: "memory");
        }
        const __half (*Kb)[FSH] = Ks[kb & 1];
        const __half (*Vb)[FSH] = Vs[kb & 1];

        float sacc[4][4];
#pragma unroll
        for (int n = 0; n < 4; n++)
#pragma unroll
            for (int r = 0; r < 4; r++) sacc[n][r] = 0.f;

#pragma unroll
        for (int kc = 0; kc < 4; kc++)
#pragma unroll
            for (int n = 0; n < 4; n++) {
                uint32_t b0 = *reinterpret_cast<const uint32_t*>(
                    &Kb[n * 8 + gid][kc * 16 + 2 * tig    ]);
                uint32_t b1 = *reinterpret_cast<const uint32_t*>(
                    &Kb[n * 8 + gid][kc * 16 + 2 * tig + 8]);
                mma_f16(sacc[n][0], sacc[n][1], sacc[n][2], sacc[n][3],
                        qf[kc][0], qf[kc][1], qf[kc][2], qf[kc][3], b0, b1);
            }

        if (kb >= 2 * qb) {
            const int rg0 = qb * 64 + w * 16 + gid;
#pragma unroll
            for (int n = 0; n < 4; n++) {
                int c = kb * KT_ + n * 8 + 2 * tig;
                if (c     > rg0    ) sacc[n][0] = -1e30f;
                if (c + 1 > rg0    ) sacc[n][1] = -1e30f;
                if (c     > rg0 + 8) sacc[n][2] = -1e30f;
                if (c + 1 > rg0 + 8) sacc[n][3] = -1e30f;
            }
        }

        float mx0 = -1e30f, mx1 = -1e30f;
#pragma unroll
        for (int n = 0; n < 4; n++) {
            mx0 = fmaxf(mx0, fmaxf(sacc[n][0], sacc[n][1]));
            mx1 = fmaxf(mx1, fmaxf(sacc[n][2], sacc[n][3]));
        }
        mx0 = fmaxf(mx0, __shfl_xor_sync(0xffffffffu, mx0, 1));
        mx0 = fmaxf(mx0, __shfl_xor_sync(0xffffffffu, mx0, 2));
        mx1 = fmaxf(mx1, __shfl_xor_sync(0xffffffffu, mx1, 1));
        mx1 = fmaxf(mx1, __shfl_xor_sync(0xffffffffu, mx1, 2));
        float mn0 = fmaxf(m0, mx0), mn1 = fmaxf(m1, mx1);
        float al0 = __expf(m0 - mn0), al1 = __expf(m1 - mn1);
        m0 = mn0; m1 = mn1;

        uint32_t pa[4], pc[4];
        float sum0 = 0.f, sum1 = 0.f;
#pragma unroll
        for (int n = 0; n < 4; n++) {
            __half2 hp0 = __floats2half2_rn(__expf(sacc[n][0] - mn0),
                                            __expf(sacc[n][1] - mn0));
            __half2 hp1 = __floats2half2_rn(__expf(sacc[n][2] - mn1),
                                            __expf(sacc[n][3] - mn1));
            float2 f0 = __half22float2(hp0);
            float2 f1 = __half22float2(hp1);
            sum0 += f0.x + f0.y;
            sum1 += f1.x + f1.y;
            pa[n] = h2u(hp0);
            pc[n] = h2u(hp1);
        }
        sum0 += __shfl_xor_sync(0xffffffffu, sum0, 1);
        sum0 += __shfl_xor_sync(0xffffffffu, sum0, 2);
        sum1 += __shfl_xor_sync(0xffffffffu, sum1, 1);
        sum1 += __shfl_xor_sync(0xffffffffu, sum1, 2);
        l0 = l0 * al0 + sum0;
        l1 = l1 * al1 + sum1;
#pragma unroll
        for (int n = 0; n < 8; n++) {
            oacc[n][0] *= al0; oacc[n][1] *= al0;
            oacc[n][2] *= al1; oacc[n][3] *= al1;
        }

#pragma unroll
        for (int kc = 0; kc < 2; kc++) {
            uint32_t a0 = pa[2 * kc];
            uint32_t a1 = pc[2 * kc];
            uint32_t a2 = pa[2 * kc + 1];
            uint32_t a3 = pc[2 * kc + 1];
            const int k0 = kc * 16 + 2 * tig;
#pragma unroll
            for (int n = 0; n < 8; n++) {
                int colh = n * 8 + gid;
                uint32_t b0 = h2u(__halves2half2(Vb[k0    ][colh], Vb[k0 + 1][colh]));
                uint32_t b1 = h2u(__halves2half2(Vb[k0 + 8][colh], Vb[k0 + 9][colh]));
                mma_f16(oacc[n][0], oacc[n][1], oacc[n][2], oacc[n][3],
                        a0, a1, a2, a3, b0, b1);
            }
        }
    }

    const float inv0 = 1.f / l0, inv1 = 1.f / l1;
    const int row0 = qb * 64 + w * 16 + gid;
#pragma unroll
    for (int n = 0; n < 8; n++) {
        int col = h * DH_ + n * 8 + 2 * tig;
        size_t o0 = ((size_t)b * T_ + row0) * E_ + col;
        size_t o1 = ((size_t)b * T_ + row0 + 8) * E_ + col;
        *reinterpret_cast<__half2*>(&g_atth[o0]) =
            __floats2half2_rn(oacc[n][0] * inv0, oacc[n][1] * inv0);
        *reinterpret_cast<__half2*>(&g_atth[o1]) =
            __floats2half2_rn(oacc[n][2] * inv1, oacc[n][3] * inv1);
    }
}

// ---------------------------------------------------------------------------
extern "C" void kernel_launch(void* const* d_in, const int* in_sizes, int n_in,
                              void* d_out, int out_size)
{
    const float* x  = (const float*)d_in[0];
    const float* wi = (const float*)d_in[1];
    const float* bi = (const float*)d_in[2];
    const float* wo = (const float*)d_in[3];
    const float* bo = (const float*)d_in[4];
    const float* wc = (const float*)d_in[5];
    const float* bc = (const float*)d_in[6];
    float* out = (float*)d_out;

    const int M = B_ * T_;  // 8192

    // weight/input prep
    cvt_xh<<<(B_ * T_ * E_ / 4 + 255) / 256, 256>>>(x);
    cvt_w<<<(E_ * E_ + 255) / 256, 256>>>(wi, wc);
    transpose_wo<<<dim3(32, 32), dim3(32, 8)>>>(wo);
    gemm_wcomb_h<<<dim3(E_ / 128, E_ / 128), 256>>>();
    bcomb_k<<<E_ / 8, 256>>>(wc, bo, bc);

    // main chain: QKV proj (fp16) -> fp16 attention -> fused projection (fp16)
    gemm_in_h<<<dim3(3 * E_ / 128, M / 256), 256>>>(bi);
    flash_attn<<<dim3(T_ / 64, B_ * H_), 128>>>();
    gemm_fin_h<<<dim3(E_ / 128, M / 256), 256>>>(out);
}